// round 1
// baseline (speedup 1.0000x reference)
#include <cuda_runtime.h>
#include <math.h>

#define BATCH 8

// ---------------- scratch (device globals; no allocation allowed) ----------------
__device__ float g_C2[96 * 96];
__device__ float g_d2[96];
__device__ float g_M[128 * 128];   // collapsed affine matrix, columns: [s0|s1|s2|s3]
__device__ float g_d[128];         // collapsed bias

__device__ float g_pool1[BATCH * 32 * 128 * 128];
__device__ float g_pool2[BATCH * 32 * 64 * 64];
__device__ float g_pool3[BATCH * 32 * 32 * 32];

__device__ float g_s0[BATCH * 32 * 256 * 256];
__device__ float g_s1[BATCH * 32 * 128 * 128];
__device__ float g_s2[BATCH * 32 * 64 * 64];
__device__ float g_s3[BATCH * 32 * 32 * 32];

__device__ float g_P3[BATCH * 128 * 32 * 32];
__device__ float g_P2[BATCH * 128 * 64 * 64];
__device__ float g_P1[BATCH * 128 * 128 * 128];

// ---------------- setup: collapse shuffle+concat+pw chain into M, d ----------------
// channel_shuffle(g=8): shuffled[c] = u[(c%8)*(C/8) + c/8]
// A1[o][j]  = W1[o][(j%8)*8   + j/8 ]   (64x64)
// B2[o][j]  = W2[o][(j%12)*8  + j/12]   (96x96)
// B3[o][j]  = W3[o][(j%16)*8  + j/16]   (128x128)
// C2 = [B2[:,:64]*A1 | B2[:,64:96]]; d2 = B2[:,:64]*b1 + b2
// M  = [B3[:,:96]*C2 | B3[:,96:128]]; d = B3[:,:96]*d2 + b3
__global__ void setup1_kernel(const float* __restrict__ w1, const float* __restrict__ b1,
                              const float* __restrict__ w2, const float* __restrict__ b2) {
    int o = blockIdx.x;    // 0..95
    int j = threadIdx.x;   // 0..95
    float acc;
    if (j < 64) {
        acc = 0.f;
        for (int k = 0; k < 64; k++) {
            float b2v = w2[o * 96 + (k % 12) * 8 + k / 12];
            float a1v = w1[k * 64 + (j % 8) * 8 + j / 8];
            acc = fmaf(b2v, a1v, acc);
        }
    } else {
        acc = w2[o * 96 + (j % 12) * 8 + j / 12];
    }
    g_C2[o * 96 + j] = acc;
    if (j == 0) {
        float s = b2[o];
        for (int k = 0; k < 64; k++)
            s = fmaf(w2[o * 96 + (k % 12) * 8 + k / 12], b1[k], s);
        g_d2[o] = s;
    }
}

__global__ void setup2_kernel(const float* __restrict__ w3, const float* __restrict__ b3) {
    int o = blockIdx.x;    // 0..127
    int j = threadIdx.x;   // 0..127
    float acc;
    if (j < 96) {
        acc = 0.f;
        for (int k = 0; k < 96; k++)
            acc = fmaf(w3[o * 128 + (k % 16) * 8 + k / 16], g_C2[k * 96 + j], acc);
    } else {
        acc = w3[o * 128 + (j % 16) * 8 + j / 16];
    }
    g_M[o * 128 + j] = acc;
    if (j == 0) {
        float s = b3[o];
        for (int k = 0; k < 96; k++)
            s = fmaf(w3[o * 128 + (k % 16) * 8 + k / 16], g_d2[k], s);
        g_d[o] = s;
    }
}

// ---------------- max pool (k x k, non-overlapping) ----------------
template <int K, int HO>
__global__ void pool_kernel(const float* __restrict__ x, int chan_off) {
    float* out = (K == 2) ? g_pool1 : (K == 4) ? g_pool2 : g_pool3;
    int idx = blockIdx.x * blockDim.x + threadIdx.x;
    constexpr int TOT = BATCH * 32 * HO * HO;
    if (idx >= TOT) return;
    int wo = idx % HO;
    int t = idx / HO;
    int ho = t % HO; t /= HO;
    int c = t & 31;
    int b = t >> 5;
    const float* src = x + ((size_t)(b * 128 + chan_off + c) * 256 + (size_t)ho * K) * 256 + (size_t)wo * K;
    float m = -3.402823466e38f;
#pragma unroll
    for (int r = 0; r < K; r++)
#pragma unroll
        for (int q = 0; q < K; q++)
            m = fmaxf(m, src[r * 256 + q]);
    out[idx] = m;
}

// ---------------- depthwise 3x3 conv (SAME, zero pad) ----------------
template <int LEVEL, int H>
__global__ void dw_kernel(const float* __restrict__ xin,
                          const float* __restrict__ w_dw, const float* __restrict__ b_dw) {
    const float* in = (LEVEL == 0) ? xin
                    : (LEVEL == 1) ? (const float*)g_pool1
                    : (LEVEL == 2) ? (const float*)g_pool2
                                   : (const float*)g_pool3;
    float* out = (LEVEL == 0) ? g_s0 : (LEVEL == 1) ? g_s1 : (LEVEL == 2) ? g_s2 : g_s3;
    constexpr int CIN = (LEVEL == 0) ? 128 : 32;  // level 0 reads channels 0..31 of x
    int idx = blockIdx.x * blockDim.x + threadIdx.x;
    constexpr int TOT = BATCH * 32 * H * H;
    if (idx >= TOT) return;
    int w = idx % H;
    int t = idx / H;
    int h = t % H; t /= H;
    int c = t & 31;
    int b = t >> 5;
    const float* wp = w_dw + (LEVEL * 32 + c) * 9;
    float acc = b_dw[LEVEL * 32 + c];
    const float* base = in + (size_t)(b * CIN + c) * H * H;
#pragma unroll
    for (int dy = -1; dy <= 1; dy++) {
        int hy = h + dy;
        if (hy < 0 || hy >= H) continue;
        const float* row = base + (size_t)hy * H;
#pragma unroll
        for (int dx = -1; dx <= 1; dx++) {
            int wx = w + dx;
            if (wx < 0 || wx >= H) continue;
            acc = fmaf(wp[(dy + 1) * 3 + (dx + 1)], row[wx], acc);
        }
    }
    out[idx] = acc;
}

// ---------------- per-pixel 128x32 GEMM + up2 accumulate (coarse->fine cascade) ----------------
template <int LEVEL, int H, int NT>
__global__ void gemm_kernel() {
    const float* s = (LEVEL == 3) ? g_s3 : (LEVEL == 2) ? g_s2 : g_s1;
    const float* Pprev = (LEVEL == 2) ? (const float*)g_P3 : (const float*)g_P2;  // unused for LEVEL==3
    float* Pout = (LEVEL == 3) ? g_P3 : (LEVEL == 2) ? g_P2 : g_P1;
    constexpr int MCOL = LEVEL * 32;
    __shared__ float Msm[128 * 32];
    for (int i = threadIdx.x; i < 128 * 32; i += NT)
        Msm[i] = g_M[(i >> 5) * 128 + MCOL + (i & 31)];
    __syncthreads();

    int p = blockIdx.x * NT + threadIdx.x;
    constexpr int PIX = H * H;
    if (p >= BATCH * PIX) return;
    int b = p / PIX;
    int hw = p % PIX;

    float sreg[32];
#pragma unroll
    for (int c = 0; c < 32; c++)
        sreg[c] = s[(size_t)(b * 32 + c) * PIX + hw];

    int hwp = 0;
    if (LEVEL < 3) {
        int h = hw / H, w = hw % H;
        hwp = (h >> 1) * (H / 2) + (w >> 1);
    }

#pragma unroll 2
    for (int o = 0; o < 128; o++) {
        float acc = (LEVEL < 3) ? Pprev[(size_t)(b * 128 + o) * (PIX / 4) + hwp] : 0.f;
        const float4* m4 = reinterpret_cast<const float4*>(Msm + o * 32);
#pragma unroll
        for (int q = 0; q < 8; q++) {
            float4 m = m4[q];
            acc = fmaf(m.x, sreg[4 * q + 0], acc);
            acc = fmaf(m.y, sreg[4 * q + 1], acc);
            acc = fmaf(m.z, sreg[4 * q + 2], acc);
            acc = fmaf(m.w, sreg[4 * q + 3], acc);
        }
        Pout[(size_t)(b * 128 + o) * PIX + hw] = acc;
    }
}

// ---------------- final: out = gelu(M0*s0 + up2(P1) + d) * x ----------------
__global__ void final_kernel(const float* __restrict__ x, float* __restrict__ out) {
    __shared__ float Msm[128 * 32];
    __shared__ float dsm[128];
    for (int i = threadIdx.x; i < 128 * 32; i += blockDim.x)
        Msm[i] = g_M[(i >> 5) * 128 + (i & 31)];
    for (int i = threadIdx.x; i < 128; i += blockDim.x)
        dsm[i] = g_d[i];
    __syncthreads();

    int p = blockIdx.x * blockDim.x + threadIdx.x;
    if (p >= BATCH * 256 * 256) return;
    int b = p >> 16;
    int hw = p & 65535;

    float sreg[32];
#pragma unroll
    for (int c = 0; c < 32; c++)
        sreg[c] = g_s0[((size_t)(b * 32 + c) << 16) + hw];

    int h = hw >> 8, w = hw & 255;
    int hwp = (h >> 1) * 128 + (w >> 1);

#pragma unroll 2
    for (int o = 0; o < 128; o++) {
        float acc = dsm[o] + g_P1[((size_t)(b * 128 + o) << 14) + hwp];
        const float4* m4 = reinterpret_cast<const float4*>(Msm + o * 32);
#pragma unroll
        for (int q = 0; q < 8; q++) {
            float4 m = m4[q];
            acc = fmaf(m.x, sreg[4 * q + 0], acc);
            acc = fmaf(m.y, sreg[4 * q + 1], acc);
            acc = fmaf(m.z, sreg[4 * q + 2], acc);
            acc = fmaf(m.w, sreg[4 * q + 3], acc);
        }
        float xv = x[((size_t)(b * 128 + o) << 16) + hw];
        float g = 0.5f * acc * (1.0f + erff(acc * 0.70710678118654752f));
        out[((size_t)(b * 128 + o) << 16) + hw] = g * xv;
    }
}

// ---------------- launch ----------------
extern "C" void kernel_launch(void* const* d_in, const int* in_sizes, int n_in,
                              void* d_out, int out_size) {
    const float* x   = (const float*)d_in[0];
    const float* wdw = (const float*)d_in[1];
    const float* bdw = (const float*)d_in[2];
    const float* w1  = (const float*)d_in[3];
    const float* b1  = (const float*)d_in[4];
    const float* w2  = (const float*)d_in[5];
    const float* b2  = (const float*)d_in[6];
    const float* w3  = (const float*)d_in[7];
    const float* b3  = (const float*)d_in[8];
    float* out = (float*)d_out;

    // collapse weight chain
    setup1_kernel<<<96, 96>>>(w1, b1, w2, b2);
    setup2_kernel<<<128, 128>>>(w3, b3);

    // pools (xc1=ch32.., xc2=ch64.., xc3=ch96..)
    pool_kernel<2, 128><<<(BATCH * 32 * 128 * 128 + 255) / 256, 256>>>(x, 32);
    pool_kernel<4, 64><<<(BATCH * 32 * 64 * 64 + 255) / 256, 256>>>(x, 64);
    pool_kernel<8, 32><<<(BATCH * 32 * 32 * 32 + 255) / 256, 256>>>(x, 96);

    // depthwise convs
    dw_kernel<0, 256><<<(BATCH * 32 * 256 * 256 + 255) / 256, 256>>>(x, wdw, bdw);
    dw_kernel<1, 128><<<(BATCH * 32 * 128 * 128 + 255) / 256, 256>>>(x, wdw, bdw);
    dw_kernel<2, 64><<<(BATCH * 32 * 64 * 64 + 255) / 256, 256>>>(x, wdw, bdw);
    dw_kernel<3, 32><<<(BATCH * 32 * 32 * 32 + 255) / 256, 256>>>(x, wdw, bdw);

    // coarse-to-fine GEMM cascade
    gemm_kernel<3, 32, 64><<<(BATCH * 32 * 32 + 63) / 64, 64>>>();
    gemm_kernel<2, 64, 256><<<(BATCH * 64 * 64 + 255) / 256, 256>>>();
    gemm_kernel<1, 128, 256><<<(BATCH * 128 * 128 + 255) / 256, 256>>>();

    // full-res fused GEMM + bias + gelu + multiply
    final_kernel<<<(BATCH * 256 * 256 + 255) / 256, 256>>>(x, out);
}

// round 4
// speedup vs baseline: 1.4569x; 1.4569x over previous
#include <cuda_runtime.h>
#include <math.h>

#define BATCH 8

// ---------------- scratch (device globals; no allocation allowed) ----------------
__device__ float g_C2[96 * 96];
__device__ float g_d2[96];
__device__ float g_M[128 * 128];    // collapsed affine matrix [o][k]
__device__ float g_Mt[128 * 128];   // transposed [k][o]
__device__ float g_d[128];          // collapsed bias

__device__ float g_pool1[BATCH * 32 * 128 * 128];
__device__ float g_pool2[BATCH * 32 * 64 * 64];
__device__ float g_pool3[BATCH * 32 * 32 * 32];

__device__ float g_s0[BATCH * 32 * 256 * 256];
__device__ float g_s1[BATCH * 32 * 128 * 128];
__device__ float g_s2[BATCH * 32 * 64 * 64];
__device__ float g_s3[BATCH * 32 * 32 * 32];

__device__ float g_P3[BATCH * 128 * 32 * 32];
__device__ float g_P2[BATCH * 128 * 64 * 64];
__device__ float g_P1[BATCH * 128 * 128 * 128];

// ---------------- f32x2 packed helpers ----------------
__device__ __forceinline__ unsigned long long pk2(float lo, float hi) {
    unsigned long long r;
    asm("mov.b64 %0, {%1,%2};" : "=l"(r) : "f"(lo), "f"(hi));
    return r;
}
__device__ __forceinline__ unsigned long long dup2(float v) { return pk2(v, v); }
__device__ __forceinline__ unsigned long long fma2(unsigned long long a, unsigned long long b,
                                                   unsigned long long c) {
    unsigned long long r;
    asm("fma.rn.f32x2 %0, %1, %2, %3;" : "=l"(r) : "l"(a), "l"(b), "l"(c));
    return r;
}
__device__ __forceinline__ float2 upk2(unsigned long long v) {
    float2 f;
    asm("mov.b64 {%0,%1}, %2;" : "=f"(f.x), "=f"(f.y) : "l"(v));
    return f;
}

// ---------------- setup: collapse shuffle+concat+pw chain into M, Mt, d ----------------
__global__ void setup1_kernel(const float* __restrict__ w1, const float* __restrict__ b1,
                              const float* __restrict__ w2, const float* __restrict__ b2) {
    int o = blockIdx.x;    // 0..95
    int j = threadIdx.x;   // 0..95
    float acc;
    if (j < 64) {
        acc = 0.f;
        for (int k = 0; k < 64; k++) {
            float b2v = w2[o * 96 + (k % 12) * 8 + k / 12];
            float a1v = w1[k * 64 + (j % 8) * 8 + j / 8];
            acc = fmaf(b2v, a1v, acc);
        }
    } else {
        acc = w2[o * 96 + (j % 12) * 8 + j / 12];
    }
    g_C2[o * 96 + j] = acc;
    if (j == 0) {
        float s = b2[o];
        for (int k = 0; k < 64; k++)
            s = fmaf(w2[o * 96 + (k % 12) * 8 + k / 12], b1[k], s);
        g_d2[o] = s;
    }
}

__global__ void setup2_kernel(const float* __restrict__ w3, const float* __restrict__ b3) {
    int o = blockIdx.x;    // 0..127
    int j = threadIdx.x;   // 0..127
    float acc;
    if (j < 96) {
        acc = 0.f;
        for (int k = 0; k < 96; k++)
            acc = fmaf(w3[o * 128 + (k % 16) * 8 + k / 16], g_C2[k * 96 + j], acc);
    } else {
        acc = w3[o * 128 + (j % 16) * 8 + j / 16];
    }
    g_M[o * 128 + j] = acc;
    g_Mt[j * 128 + o] = acc;
    if (j == 0) {
        float s = b3[o];
        for (int k = 0; k < 96; k++)
            s = fmaf(w3[o * 128 + (k % 16) * 8 + k / 16], g_d2[k], s);
        g_d[o] = s;
    }
}

// ---------------- vectorized max pools ----------------
__global__ void pool1_kernel(const float* __restrict__ x) {  // k=2, HO=128, 2 outputs/thread
    int idx = blockIdx.x * blockDim.x + threadIdx.x;
    const int TOT = BATCH * 32 * 128 * 64;
    if (idx >= TOT) return;
    int wp = idx & 63;        // output pair id
    int t = idx >> 6;
    int ho = t & 127; t >>= 7;
    int c = t & 31;
    int b = t >> 5;
    const float* src = x + ((size_t)(b * 128 + 32 + c) * 256 + (size_t)ho * 2) * 256 + (size_t)wp * 4;
    float4 r0 = *(const float4*)src;
    float4 r1 = *(const float4*)(src + 256);
    float2 o2;
    o2.x = fmaxf(fmaxf(r0.x, r0.y), fmaxf(r1.x, r1.y));
    o2.y = fmaxf(fmaxf(r0.z, r0.w), fmaxf(r1.z, r1.w));
    *(float2*)&g_pool1[(size_t)idx * 2] = o2;
}

__global__ void pool2_kernel(const float* __restrict__ x) {  // k=4, HO=64
    int idx = blockIdx.x * blockDim.x + threadIdx.x;
    const int TOT = BATCH * 32 * 64 * 64;
    if (idx >= TOT) return;
    int wo = idx & 63;
    int t = idx >> 6;
    int ho = t & 63; t >>= 6;
    int c = t & 31;
    int b = t >> 5;
    const float* src = x + ((size_t)(b * 128 + 64 + c) * 256 + (size_t)ho * 4) * 256 + (size_t)wo * 4;
    float m = -3.402823466e38f;
#pragma unroll
    for (int r = 0; r < 4; r++) {
        float4 v = *(const float4*)(src + r * 256);
        m = fmaxf(m, fmaxf(fmaxf(v.x, v.y), fmaxf(v.z, v.w)));
    }
    g_pool2[idx] = m;
}

__global__ void pool3_kernel(const float* __restrict__ x) {  // k=8, HO=32
    int idx = blockIdx.x * blockDim.x + threadIdx.x;
    const int TOT = BATCH * 32 * 32 * 32;
    if (idx >= TOT) return;
    int wo = idx & 31;
    int t = idx >> 5;
    int ho = t & 31; t >>= 5;
    int c = t & 31;
    int b = t >> 5;
    const float* src = x + ((size_t)(b * 128 + 96 + c) * 256 + (size_t)ho * 8) * 256 + (size_t)wo * 8;
    float m = -3.402823466e38f;
#pragma unroll
    for (int r = 0; r < 8; r++) {
        float4 v0 = *(const float4*)(src + r * 256);
        float4 v1 = *(const float4*)(src + r * 256 + 4);
        m = fmaxf(m, fmaxf(fmaxf(v0.x, v0.y), fmaxf(v0.z, v0.w)));
        m = fmaxf(m, fmaxf(fmaxf(v1.x, v1.y), fmaxf(v1.z, v1.w)));
    }
    g_pool3[idx] = m;
}

// ---------------- depthwise 3x3 conv, 4 outputs per thread ----------------
template <int LEVEL, int H>
__global__ void dw_kernel(const float* __restrict__ xin,
                          const float* __restrict__ w_dw, const float* __restrict__ b_dw) {
    const float* in = (LEVEL == 0) ? xin
                    : (LEVEL == 1) ? (const float*)g_pool1
                    : (LEVEL == 2) ? (const float*)g_pool2
                                   : (const float*)g_pool3;
    float* out = (LEVEL == 0) ? g_s0 : (LEVEL == 1) ? g_s1 : (LEVEL == 2) ? g_s2 : g_s3;
    constexpr int CIN = (LEVEL == 0) ? 128 : 32;
    int idx = blockIdx.x * blockDim.x + threadIdx.x;
    constexpr int W4 = H / 4;
    constexpr int TOT = BATCH * 32 * H * W4;
    if (idx >= TOT) return;
    int w4 = (idx % W4) * 4;
    int t = idx / W4;
    int h = t % H; t /= H;
    int c = t & 31;
    int b = t >> 5;
    const float* wp = w_dw + (LEVEL * 32 + c) * 9;
    float w00 = wp[0], w01 = wp[1], w02 = wp[2];
    float w10 = wp[3], w11 = wp[4], w12 = wp[5];
    float w20 = wp[6], w21 = wp[7], w22 = wp[8];
    float bias = b_dw[LEVEL * 32 + c];
    float a0 = bias, a1 = bias, a2 = bias, a3 = bias;
    const float* base = in + (size_t)(b * CIN + c) * H * H;
#pragma unroll
    for (int dy = -1; dy <= 1; dy++) {
        int hy = h + dy;
        if (hy < 0 || hy >= H) continue;
        const float* row = base + (size_t)hy * H;
        float4 C = *(const float4*)(row + w4);
        float lft = (w4 > 0) ? row[w4 - 1] : 0.f;
        float rgt = (w4 + 4 < H) ? row[w4 + 4] : 0.f;
        float k0 = (dy == -1) ? w00 : (dy == 0) ? w10 : w20;
        float k1 = (dy == -1) ? w01 : (dy == 0) ? w11 : w21;
        float k2 = (dy == -1) ? w02 : (dy == 0) ? w12 : w22;
        a0 = fmaf(k0, lft, fmaf(k1, C.x, fmaf(k2, C.y, a0)));
        a1 = fmaf(k0, C.x, fmaf(k1, C.y, fmaf(k2, C.z, a1)));
        a2 = fmaf(k0, C.y, fmaf(k1, C.z, fmaf(k2, C.w, a2)));
        a3 = fmaf(k0, C.z, fmaf(k1, C.w, fmaf(k2, rgt, a3)));
    }
    float4 r;
    r.x = a0; r.y = a1; r.z = a2; r.w = a3;
    *(float4*)&out[(size_t)idx * 4] = r;
}

// ---------------- tiled 128x32 GEMM + up2 accumulate (cascade levels 1..3) ----------------
// Block: 128 threads, tile = 128 outputs x 64 pixels (one strip of 64 consecutive hw).
// Thread: to = tid>>3 (8 outputs), tp = tid&7 (8 pixels = 4 f32x2 pairs). FFMA2 mainloop.
template <int LEVEL, int H>
__global__ void gemm_tiled() {
    constexpr int PIX = H * H;
    constexpr int CPIX = PIX / 4;
    constexpr int CP = (H >= 64) ? 32 : 16;
    const float* S = (LEVEL == 3) ? g_s3 : (LEVEL == 2) ? g_s2 : g_s1;
    const float* Pprev = (LEVEL == 2) ? (const float*)g_P3 : (const float*)g_P2;
    float* Pout = (LEVEL == 3) ? g_P3 : (LEVEL == 2) ? g_P2 : g_P1;

    __shared__ float Msm[32 * 128];
    __shared__ float Ssm[32 * 64];
    __shared__ float Psm[128 * CP];

    int blk = blockIdx.x;
    int b = blk / (PIX / 64);
    int hw0 = (blk % (PIX / 64)) * 64;
    int tid = threadIdx.x;

    for (int i = tid * 4; i < 32 * 128; i += 512)
        *(float4*)&Msm[i] = *(const float4*)&g_Mt[(LEVEL * 32 + (i >> 7)) * 128 + (i & 127)];
    for (int i = tid * 4; i < 32 * 64; i += 512) {
        int k = i >> 6, p = i & 63;
        *(float4*)&Ssm[i] = *(const float4*)&S[(size_t)(b * 32 + k) * PIX + hw0 + p];
    }
    if (LEVEL < 3) {
        int h = hw0 / H;
        int w0 = hw0 % H;
        int cbase = (h >> 1) * (H / 2) + (w0 >> 1);
        for (int i = tid * 4; i < 128 * CP; i += 512) {
            int o = i / CP, cp = i % CP;
            *(float4*)&Psm[i] = *(const float4*)&Pprev[(size_t)(b * 128 + o) * CPIX + cbase + cp];
        }
    }
    __syncthreads();

    int to = tid >> 3;   // 0..15 -> outputs to*8..to*8+7
    int tp = tid & 7;    // 0..7  -> pixels  tp*8..tp*8+7

    unsigned long long acc[8][4];
#pragma unroll
    for (int i = 0; i < 8; i++)
#pragma unroll
        for (int j = 0; j < 4; j++) acc[i][j] = 0ULL;

#pragma unroll 4
    for (int k = 0; k < 32; k++) {
        float4 ma = *(const float4*)&Msm[k * 128 + to * 8];
        float4 mb = *(const float4*)&Msm[k * 128 + to * 8 + 4];
        float4 sa = *(const float4*)&Ssm[k * 64 + tp * 8];
        float4 sb = *(const float4*)&Ssm[k * 64 + tp * 8 + 4];
        unsigned long long sp[4] = {pk2(sa.x, sa.y), pk2(sa.z, sa.w),
                                    pk2(sb.x, sb.y), pk2(sb.z, sb.w)};
        float mv[8] = {ma.x, ma.y, ma.z, ma.w, mb.x, mb.y, mb.z, mb.w};
#pragma unroll
        for (int o8 = 0; o8 < 8; o8++) {
            unsigned long long md = dup2(mv[o8]);
#pragma unroll
            for (int pp = 0; pp < 4; pp++) acc[o8][pp] = fma2(sp[pp], md, acc[o8][pp]);
        }
    }

    int cpb = (H >= 64) ? tp * 4 : (tp & 3) * 4;
#pragma unroll
    for (int o8 = 0; o8 < 8; o8++) {
        int o = to * 8 + o8;
        float p0 = 0.f, p1 = 0.f, p2 = 0.f, p3 = 0.f;
        if (LEVEL < 3) {
            p0 = Psm[o * CP + cpb + 0];
            p1 = Psm[o * CP + cpb + 1];
            p2 = Psm[o * CP + cpb + 2];
            p3 = Psm[o * CP + cpb + 3];
        }
        float2 v0 = upk2(acc[o8][0]), v1 = upk2(acc[o8][1]);
        float2 v2 = upk2(acc[o8][2]), v3 = upk2(acc[o8][3]);
        float4 r0, r1;
        r0.x = v0.x + p0; r0.y = v0.y + p0; r0.z = v1.x + p1; r0.w = v1.y + p1;
        r1.x = v2.x + p2; r1.y = v2.y + p2; r1.z = v3.x + p3; r1.w = v3.y + p3;
        float* dst = Pout + (size_t)(b * 128 + o) * PIX + hw0 + tp * 8;
        *(float4*)dst = r0;
        *(float4*)(dst + 4) = r1;
    }
}

// ---------------- final: out = gelu(M0*s0 + up2(P1) + d) * x, tiled ----------------
__global__ void final_kernel(const float* __restrict__ x, float* __restrict__ out) {
    __shared__ float Msm[32 * 128];
    __shared__ float Ssm[32 * 64];
    __shared__ float Psm[128 * 32];
    __shared__ float dsm[128];

    int blk = blockIdx.x;
    int b = blk >> 10;
    int hw0 = (blk & 1023) * 64;
    int tid = threadIdx.x;

    for (int i = tid * 4; i < 32 * 128; i += 512)
        *(float4*)&Msm[i] = *(const float4*)&g_Mt[(i >> 7) * 128 + (i & 127)];
    for (int i = tid * 4; i < 32 * 64; i += 512) {
        int k = i >> 6, p = i & 63;
        *(float4*)&Ssm[i] = *(const float4*)&g_s0[(((size_t)(b * 32 + k)) << 16) + hw0 + p];
    }
    {
        int h = hw0 >> 8;
        int w0 = hw0 & 255;
        int cbase = (h >> 1) * 128 + (w0 >> 1);
        for (int i = tid * 4; i < 128 * 32; i += 512) {
            int o = i >> 5, cp = i & 31;
            *(float4*)&Psm[i] = *(const float4*)&g_P1[(((size_t)(b * 128 + o)) << 14) + cbase + cp];
        }
    }
    if (tid < 128) dsm[tid] = g_d[tid];
    __syncthreads();

    int to = tid >> 3;
    int tp = tid & 7;

    unsigned long long acc[8][4];
#pragma unroll
    for (int i = 0; i < 8; i++)
#pragma unroll
        for (int j = 0; j < 4; j++) acc[i][j] = 0ULL;

#pragma unroll 4
    for (int k = 0; k < 32; k++) {
        float4 ma = *(const float4*)&Msm[k * 128 + to * 8];
        float4 mb = *(const float4*)&Msm[k * 128 + to * 8 + 4];
        float4 sa = *(const float4*)&Ssm[k * 64 + tp * 8];
        float4 sb = *(const float4*)&Ssm[k * 64 + tp * 8 + 4];
        unsigned long long sp[4] = {pk2(sa.x, sa.y), pk2(sa.z, sa.w),
                                    pk2(sb.x, sb.y), pk2(sb.z, sb.w)};
        float mv[8] = {ma.x, ma.y, ma.z, ma.w, mb.x, mb.y, mb.z, mb.w};
#pragma unroll
        for (int o8 = 0; o8 < 8; o8++) {
            unsigned long long md = dup2(mv[o8]);
#pragma unroll
            for (int pp = 0; pp < 4; pp++) acc[o8][pp] = fma2(sp[pp], md, acc[o8][pp]);
        }
    }

    int cpb = tp * 4;
#pragma unroll
    for (int o8 = 0; o8 < 8; o8++) {
        int o = to * 8 + o8;
        float dv = dsm[o];
        float p0 = Psm[o * 32 + cpb + 0] + dv;
        float p1 = Psm[o * 32 + cpb + 1] + dv;
        float p2 = Psm[o * 32 + cpb + 2] + dv;
        float p3 = Psm[o * 32 + cpb + 3] + dv;
        float2 v0 = upk2(acc[o8][0]), v1 = upk2(acc[o8][1]);
        float2 v2 = upk2(acc[o8][2]), v3 = upk2(acc[o8][3]);
        float a[8] = {v0.x + p0, v0.y + p0, v1.x + p1, v1.y + p1,
                      v2.x + p2, v2.y + p2, v3.x + p3, v3.y + p3};
        size_t off = (((size_t)(b * 128 + o)) << 16) + hw0 + tp * 8;
        float4 x0 = *(const float4*)&x[off];
        float4 x1 = *(const float4*)&x[off + 4];
        float xv[8] = {x0.x, x0.y, x0.z, x0.w, x1.x, x1.y, x1.z, x1.w};
        float r[8];
#pragma unroll
        for (int j = 0; j < 8; j++) {
            float g = 0.5f * a[j] * (1.0f + erff(a[j] * 0.70710678118654752f));
            r[j] = g * xv[j];
        }
        float4 r0, r1;
        r0.x = r[0]; r0.y = r[1]; r0.z = r[2]; r0.w = r[3];
        r1.x = r[4]; r1.y = r[5]; r1.z = r[6]; r1.w = r[7];
        *(float4*)&out[off] = r0;
        *(float4*)&out[off + 4] = r1;
    }
}

// ---------------- launch ----------------
extern "C" void kernel_launch(void* const* d_in, const int* in_sizes, int n_in,
                              void* d_out, int out_size) {
    const float* x   = (const float*)d_in[0];
    const float* wdw = (const float*)d_in[1];
    const float* bdw = (const float*)d_in[2];
    const float* w1  = (const float*)d_in[3];
    const float* b1  = (const float*)d_in[4];
    const float* w2  = (const float*)d_in[5];
    const float* b2  = (const float*)d_in[6];
    const float* w3  = (const float*)d_in[7];
    const float* b3  = (const float*)d_in[8];
    float* out = (float*)d_out;

    setup1_kernel<<<96, 96>>>(w1, b1, w2, b2);
    setup2_kernel<<<128, 128>>>(w3, b3);

    pool1_kernel<<<(BATCH * 32 * 128 * 64 + 255) / 256, 256>>>(x);
    pool2_kernel<<<(BATCH * 32 * 64 * 64 + 255) / 256, 256>>>(x);
    pool3_kernel<<<(BATCH * 32 * 32 * 32 + 255) / 256, 256>>>(x);

    dw_kernel<0, 256><<<(BATCH * 32 * 256 * 64 + 255) / 256, 256>>>(x, wdw, bdw);
    dw_kernel<1, 128><<<(BATCH * 32 * 128 * 32 + 255) / 256, 256>>>(x, wdw, bdw);
    dw_kernel<2, 64><<<(BATCH * 32 * 64 * 16 + 255) / 256, 256>>>(x, wdw, bdw);
    dw_kernel<3, 32><<<(BATCH * 32 * 32 * 8 + 255) / 256, 256>>>(x, wdw, bdw);

    gemm_tiled<3, 32><<<BATCH * (32 * 32 / 64), 128>>>();
    gemm_tiled<2, 64><<<BATCH * (64 * 64 / 64), 128>>>();
    gemm_tiled<1, 128><<<BATCH * (128 * 128 / 64), 128>>>();

    final_kernel<<<BATCH * 1024, 128>>>(x, out);
}